// round 11
// baseline (speedup 1.0000x reference)
#include <cuda_runtime.h>
#include <cuda_fp16.h>
#include <math.h>

#define HIDDEN   1024
#define HEADS    16
#define HEAD_DIM 64
#define BATCH    2
#define SEQ      2048
#define MROWS    (BATCH * SEQ)   // 4096

// Scratch (no cudaMalloc allowed)
__device__ __half g_xh[MROWS * HIDDEN];
__device__ __half g_q[MROWS * HIDDEN];
__device__ __half g_k[MROWS * HIDDEN];
__device__ __half g_v[MROWS * HIDDEN];
__device__ __half g_ctx[MROWS * HIDDEN];
__device__ __half g_wtq[HIDDEN * HIDDEN];
__device__ __half g_wtk[HIDDEN * HIDDEN];
__device__ __half g_wtv[HIDDEN * HIDDEN];
__device__ __half g_wto[HIDDEN * HIDDEN];

// ---------------------------------------------------------------------------
__device__ __forceinline__ unsigned smem_u32(const void* p) {
    unsigned a;
    asm("{ .reg .u64 t; cvta.to.shared.u64 t, %1; cvt.u32.u64 %0, t; }"
        : "=r"(a) : "l"(p));
    return a;
}

__device__ __forceinline__ unsigned pack_h2(float a, float b) {
    __half2 h = __floats2half2_rn(a, b);
    return *(unsigned*)&h;
}

__device__ __forceinline__ float ex2f(float x) {
    float r;
    asm("ex2.approx.f32 %0, %1;" : "=f"(r) : "f"(x));
    return r;
}

#define CP_ASYNC16(dst, src) \
    asm volatile("cp.async.cg.shared.global [%0], [%1], 16;" \
                 :: "r"(dst), "l"(src) : "memory")
#define CP_COMMIT() asm volatile("cp.async.commit_group;" ::: "memory")
#define CP_WAIT1()  asm volatile("cp.async.wait_group 1;" ::: "memory")
#define CP_WAIT0()  asm volatile("cp.async.wait_group 0;" ::: "memory")

#define LDMX4(r0, r1, r2, r3, addr) \
    asm volatile("ldmatrix.sync.aligned.m8n8.x4.shared.b16 {%0,%1,%2,%3}, [%4];" \
                 : "=r"(r0), "=r"(r1), "=r"(r2), "=r"(r3) : "r"(addr))
#define LDMX4T(r0, r1, r2, r3, addr) \
    asm volatile("ldmatrix.sync.aligned.m8n8.x4.trans.shared.b16 {%0,%1,%2,%3}, [%4];" \
                 : "=r"(r0), "=r"(r1), "=r"(r2), "=r"(r3) : "r"(addr))

// NOTE: non-volatile — pure register op, lets the compiler schedule HMMA
// freely around (volatile) LDSM/cp.async.
__device__ __forceinline__ void mma_f16(float* d,
                                        unsigned a0, unsigned a1, unsigned a2, unsigned a3,
                                        unsigned b0, unsigned b1) {
    asm("mma.sync.aligned.m16n8k16.row.col.f32.f16.f16.f32 "
        "{%0,%1,%2,%3}, {%4,%5,%6,%7}, {%8,%9}, {%0,%1,%2,%3};\n"
        : "+f"(d[0]), "+f"(d[1]), "+f"(d[2]), "+f"(d[3])
        : "r"(a0), "r"(a1), "r"(a2), "r"(a3), "r"(b0), "r"(b1));
}

// ---------------------------------------------------------------------------
// Prep (one launch): z=0..3 -> weight transpose+fp16; z=4 -> x fp32->fp16
// ---------------------------------------------------------------------------
__global__ void __launch_bounds__(256) prep_kernel(
    const float* __restrict__ x, __half* __restrict__ xh,
    const float* __restrict__ s0, const float* __restrict__ s1,
    const float* __restrict__ s2, const float* __restrict__ s3,
    __half* __restrict__ d0, __half* __restrict__ d1,
    __half* __restrict__ d2, __half* __restrict__ d3)
{
    if (blockIdx.z == 4) {
        const int bid = blockIdx.y * 32 + blockIdx.x;
        const int tid = threadIdx.y * 32 + threadIdx.x;
        const size_t i = ((size_t)bid * 256 + tid) * 16;
        #pragma unroll
        for (int p = 0; p < 2; p++) {
            float4 a = *(const float4*)(x + i + 8 * p);
            float4 b = *(const float4*)(x + i + 8 * p + 4);
            uint4 u;
            u.x = pack_h2(a.x, a.y);
            u.y = pack_h2(a.z, a.w);
            u.z = pack_h2(b.x, b.y);
            u.w = pack_h2(b.z, b.w);
            *(uint4*)(xh + i + 8 * p) = u;
        }
        return;
    }
    const float* S;
    __half* D;
    switch (blockIdx.z) {
        case 0: S = s0; D = d0; break;
        case 1: S = s1; D = d1; break;
        case 2: S = s2; D = d2; break;
        default: S = s3; D = d3; break;
    }
    __shared__ float t[32][33];
    const int bx = blockIdx.x * 32, by = blockIdx.y * 32;
    #pragma unroll
    for (int i = 0; i < 4; i++)
        t[threadIdx.y + 8 * i][threadIdx.x] =
            S[(size_t)(by + threadIdx.y + 8 * i) * HIDDEN + bx + threadIdx.x];
    __syncthreads();
    #pragma unroll
    for (int i = 0; i < 4; i++)
        D[(size_t)(bx + threadIdx.y + 8 * i) * HIDDEN + by + threadIdx.x] =
            __float2half(t[threadIdx.x][threadIdx.y + 8 * i]);
}

// ---------------------------------------------------------------------------
// fp16 GEMM, z-fused: C_z = (Ah @ Bt_z^T + bias_z) * scale_z
// CTA tile 256x128, BK=64, 8 warps (4x2) each 64x64 -> half the smem
// crossbar bytes per HMMA. 3-stage cp.async ring. 1 CTA/SM, 255-reg budget.
// ---------------------------------------------------------------------------
#define GM 256
#define GN 128
#define GSTRIDE 144
#define G_ASZ (GM * GSTRIDE)        // 36864
#define G_BSZ (GN * GSTRIDE)        // 18432
#define G_STG (G_ASZ + G_BSZ)       // 55296
#define G_SMEM (3 * G_STG)          // 165888

__global__ void __launch_bounds__(256, 1) gemm_h_kernel(
    const __half* __restrict__ Ah,
    const __half* __restrict__ B0, const __half* __restrict__ B1,
    const __half* __restrict__ B2,
    const float* __restrict__ bias0, const float* __restrict__ bias1,
    const float* __restrict__ bias2,
    void* __restrict__ C0, void* __restrict__ C1, void* __restrict__ C2,
    int out_half, float scale0)
{
    const __half* Bt;
    const float* bias;
    void* Cout;
    float scale = 1.0f;
    switch (blockIdx.z) {
        case 0:  Bt = B0; bias = bias0; Cout = C0; scale = scale0; break;
        case 1:  Bt = B1; bias = bias1; Cout = C1; break;
        default: Bt = B2; bias = bias2; Cout = C2; break;
    }

    extern __shared__ __align__(16) char smem[];
    const unsigned sbase = smem_u32(smem);
    const int tid  = threadIdx.x;
    const int lane = tid & 31;
    const int wid  = tid >> 5;
    const int g = lane >> 2, c = lane & 3;
    const int wm = (wid >> 1) * 64;      // 4 warp-rows
    const int wn = (wid & 1) * 64;       // 2 warp-cols
    const int bm = blockIdx.y * GM;
    const int bn = blockIdx.x * GN;

    const unsigned a_lm = (unsigned)(wm + (lane & 15)) * GSTRIDE + (lane >> 4) * 16;
    const unsigned b_lm = (unsigned)(wn + (lane & 7)) * GSTRIDE + ((lane >> 3) & 1) * 16
                        + (lane >> 4) * 8 * GSTRIDE;

    // loaders: A row tid (8x16B); B row tid>>1, half (tid&1) (4x16B)
    const __half* Asrc = Ah + (size_t)(bm + tid) * HIDDEN;
    const __half* Bsrc = Bt + (size_t)(bn + (tid >> 1)) * HIDDEN + (tid & 1) * 32;
    const unsigned a_dst0 = sbase + tid * GSTRIDE;
    const unsigned b_dst0 = sbase + G_ASZ + (tid >> 1) * GSTRIDE + (tid & 1) * 64;

    // prologue: prefetch chunks 0,1 into stages 0,1
    #pragma unroll
    for (int p = 0; p < 2; p++) {
        const unsigned so = p * G_STG;
        const int k0 = p * 64;
        #pragma unroll
        for (int j = 0; j < 8; j++)
            CP_ASYNC16(a_dst0 + so + 16 * j, (const char*)(Asrc + k0) + 16 * j);
        #pragma unroll
        for (int j = 0; j < 4; j++)
            CP_ASYNC16(b_dst0 + so + 16 * j, (const char*)(Bsrc + k0) + 16 * j);
        CP_COMMIT();
    }

    float acc[4][8][4] = {};

    for (int i = 0; i < 16; i++) {
        const int st = i % 3;
        if (i < 15) CP_WAIT1(); else CP_WAIT0();
        __syncthreads();
        if (i < 14) {
            const unsigned so = ((i + 2) % 3) * G_STG;
            const int k1 = (i + 2) * 64;
            #pragma unroll
            for (int j = 0; j < 8; j++)
                CP_ASYNC16(a_dst0 + so + 16 * j, (const char*)(Asrc + k1) + 16 * j);
            #pragma unroll
            for (int j = 0; j < 4; j++)
                CP_ASYNC16(b_dst0 + so + 16 * j, (const char*)(Bsrc + k1) + 16 * j);
            CP_COMMIT();
        }

        const unsigned a_s = sbase + st * G_STG;
        const unsigned b_s = a_s + G_ASZ;
        #pragma unroll
        for (int kk = 0; kk < 4; kk++) {
            unsigned af[4][4], bf[4][4];
            #pragma unroll
            for (int mi = 0; mi < 4; mi++)
                LDMX4(af[mi][0], af[mi][1], af[mi][2], af[mi][3],
                      a_s + a_lm + mi * 16 * GSTRIDE + kk * 32);
            #pragma unroll
            for (int jj = 0; jj < 4; jj++)
                LDMX4(bf[jj][0], bf[jj][1], bf[jj][2], bf[jj][3],
                      b_s + b_lm + jj * 16 * GSTRIDE + kk * 32);
            #pragma unroll
            for (int mi = 0; mi < 4; mi++)
                #pragma unroll
                for (int j = 0; j < 8; j++) {
                    const unsigned* b2 = &bf[j >> 1][(j & 1) * 2];
                    mma_f16(acc[mi][j], af[mi][0], af[mi][1], af[mi][2], af[mi][3],
                            b2[0], b2[1]);
                }
        }
    }

    #pragma unroll
    for (int j = 0; j < 8; j++) {
        int col = bn + wn + 8 * j + 2 * c;
        float2 b2 = *(const float2*)(bias + col);
        #pragma unroll
        for (int mi = 0; mi < 4; mi++) {
            int row = bm + wm + 16 * mi + g;
            float v00 = (acc[mi][j][0] + b2.x) * scale;
            float v01 = (acc[mi][j][1] + b2.y) * scale;
            float v10 = (acc[mi][j][2] + b2.x) * scale;
            float v11 = (acc[mi][j][3] + b2.y) * scale;
            if (out_half) {
                __half* C = (__half*)Cout;
                *(unsigned*)(C + (size_t)row * HIDDEN + col)       = pack_h2(v00, v01);
                *(unsigned*)(C + (size_t)(row + 8) * HIDDEN + col) = pack_h2(v10, v11);
            } else {
                float* C = (float*)Cout;
                *(float2*)(C + (size_t)row * HIDDEN + col)       = make_float2(v00, v01);
                *(float2*)(C + (size_t)(row + 8) * HIDDEN + col) = make_float2(v10, v11);
            }
        }
    }
}

// ---------------------------------------------------------------------------
// Flash attention: 8 warps x 16 q rows, fp16 mma, MUFU/HMMA-interleaved
// streaming softmax, 3-stage cp.async ring (unchanged from round 10 best).
// ---------------------------------------------------------------------------
#define ASTRIDE 144
#define ATILE   (64 * ASTRIDE)   // 9216
#define A_SMEM  (6 * ATILE)      // 55296

__global__ void __launch_bounds__(256, 2) attn_h_kernel(
    const __half* __restrict__ Q, const __half* __restrict__ K,
    const __half* __restrict__ V, __half* __restrict__ Octx)
{
    extern __shared__ __align__(16) char smem[];
    const unsigned sbase = smem_u32(smem);

    const int tid  = threadIdx.x;
    const int lane = tid & 31;
    const int w    = tid >> 5;
    const int g = lane >> 2, c = lane & 3;
    const int bh = blockIdx.y;
    const int b = bh >> 4;
    const int h = bh & 15;
    const int q0 = blockIdx.x * 128;

    const __half* Qb = Q + (size_t)b * SEQ * HIDDEN + h * HEAD_DIM;
    const __half* Kb = K + (size_t)b * SEQ * HIDDEN + h * HEAD_DIM;
    const __half* Vb = V + (size_t)b * SEQ * HIDDEN + h * HEAD_DIM;

    const unsigned lm16 = (unsigned)(lane & 15) * ASTRIDE + (lane >> 4) * 16;
    const unsigned lmB  = (unsigned)(lane & 7) * ASTRIDE + ((lane >> 3) & 1) * 16
                        + (lane >> 4) * 8 * ASTRIDE;

    // ---- stage Q through smem (two 64-row halves), fragments in regs ----
    unsigned qa[4][4];
    {
        const int lr = tid >> 2;
        const int ls = tid & 3;
        #pragma unroll
        for (int half = 0; half < 2; half++) {
            __syncthreads();
            #pragma unroll
            for (int s = 0; s < 2; s++) {
                uint4 u = *(const uint4*)(Qb + (size_t)(q0 + 64 * half + lr) * HIDDEN + ls * 16 + 8 * s);
                *(uint4*)(smem + lr * ASTRIDE + ls * 32 + 16 * s) = u;
            }
            __syncthreads();
            if ((w >> 2) == half) {
                unsigned base = sbase + (unsigned)(w & 3) * 16 * ASTRIDE + lm16;
                #pragma unroll
                for (int kk = 0; kk < 4; kk++)
                    LDMX4(qa[kk][0], qa[kk][1], qa[kk][2], qa[kk][3], base + kk * 32);
            }
        }
        __syncthreads();
    }

    // pipeline loaders: 4 threads per row, 64 rows
    const int lr = tid >> 2;
    const int ls = tid & 3;
    const unsigned k_dst0 = sbase + lr * ASTRIDE + ls * 32;
    const unsigned v_dst0 = k_dst0 + ATILE;
    const __half* Ksrc = Kb + (size_t)lr * HIDDEN + ls * 16;
    const __half* Vsrc = Vb + (size_t)lr * HIDDEN + ls * 16;

    #pragma unroll
    for (int p = 0; p < 2; p++) {
        const unsigned so = p * 2 * ATILE;
        const size_t koff = (size_t)p * 64 * HIDDEN;
        #pragma unroll
        for (int s = 0; s < 2; s++) {
            CP_ASYNC16(k_dst0 + so + 16 * s, (const char*)(Ksrc + koff) + 16 * s);
            CP_ASYNC16(v_dst0 + so + 16 * s, (const char*)(Vsrc + koff) + 16 * s);
        }
        CP_COMMIT();
    }

    const unsigned onesB = (g == 0) ? 0x3C003C00u : 0u;
    const int NT = SEQ / 64;   // 32

    float o[8][4] = {};
    float ol[4] = {};

    for (int t = 0; t < NT; t++) {
        const int st = t % 3;
        if (t < NT - 1) CP_WAIT1(); else CP_WAIT0();
        __syncthreads();

        const unsigned ks = sbase + st * 2 * ATILE;
        const unsigned vs = ks + ATILE;

        // S = Q @ K^T (scores pre-scaled by 0.125*log2e via Q GEMM)
        float s[8][4] = {};
        #pragma unroll
        for (int kk = 0; kk < 4; kk++) {
            #pragma unroll
            for (int jj = 0; jj < 4; jj++) {
                unsigned bf0, bf1, bf2, bf3;
                LDMX4(bf0, bf1, bf2, bf3, ks + lmB + (unsigned)jj * 16 * ASTRIDE + kk * 32);
                mma_f16(s[2 * jj + 0], qa[kk][0], qa[kk][1], qa[kk][2], qa[kk][3], bf0, bf1);
                mma_f16(s[2 * jj + 1], qa[kk][0], qa[kk][1], qa[kk][2], qa[kk][3], bf2, bf3);
            }
        }

        // prefetch tile t+2 between S and PV
        if (t < NT - 2) {
            const unsigned so = ((t + 2) % 3) * 2 * ATILE;
            const size_t koff = (size_t)(t + 2) * 64 * HIDDEN;
            #pragma unroll
            for (int s2 = 0; s2 < 2; s2++) {
                CP_ASYNC16(k_dst0 + so + 16 * s2, (const char*)(Ksrc + koff) + 16 * s2);
                CP_ASYNC16(v_dst0 + so + 16 * s2, (const char*)(Vsrc + koff) + 16 * s2);
            }
            CP_COMMIT();
        }

        // fused softmax + PV: MUFU/pack interleave with 9 HMMA per kk
        #pragma unroll
        for (int kk = 0; kk < 4; kk++) {
            unsigned vf[4][4];
            #pragma unroll
            for (int dj = 0; dj < 4; dj++)
                LDMX4T(vf[dj][0], vf[dj][1], vf[dj][2], vf[dj][3],
                       vs + (unsigned)kk * 16 * ASTRIDE + lm16 + dj * 32);
            unsigned pa0 = pack_h2(ex2f(s[2 * kk][0]),     ex2f(s[2 * kk][1]));
            unsigned pa1 = pack_h2(ex2f(s[2 * kk][2]),     ex2f(s[2 * kk][3]));
            unsigned pa2 = pack_h2(ex2f(s[2 * kk + 1][0]), ex2f(s[2 * kk + 1][1]));
            unsigned pa3 = pack_h2(ex2f(s[2 * kk + 1][2]), ex2f(s[2 * kk + 1][3]));
            #pragma unroll
            for (int dj = 0; dj < 4; dj++) {
                mma_f16(o[2 * dj + 0], pa0, pa1, pa2, pa3, vf[dj][0], vf[dj][1]);
                mma_f16(o[2 * dj + 1], pa0, pa1, pa2, pa3, vf[dj][2], vf[dj][3]);
            }
            mma_f16(ol, pa0, pa1, pa2, pa3, onesB, onesB);
        }
    }

    const int qbase = lane & ~3;
    float l0 = __shfl_sync(0xffffffffu, ol[0], qbase);
    float l1 = __shfl_sync(0xffffffffu, ol[2], qbase);
    float inv0 = 1.f / l0;
    float inv1 = 1.f / l1;

    __half* Ob = Octx + ((size_t)b * SEQ + q0 + w * 16) * HIDDEN + h * HEAD_DIM;
    #pragma unroll
    for (int n = 0; n < 8; n++) {
        int col = 8 * n + 2 * c;
        *(unsigned*)(Ob + (size_t)g * HIDDEN + col) =
            pack_h2(o[n][0] * inv0, o[n][1] * inv0);
        *(unsigned*)(Ob + (size_t)(g + 8) * HIDDEN + col) =
            pack_h2(o[n][2] * inv1, o[n][3] * inv1);
    }
}

// ---------------------------------------------------------------------------
extern "C" void kernel_launch(void* const* d_in, const int* in_sizes, int n_in,
                              void* d_out, int out_size)
{
    const float* x  = (const float*)d_in[0];
    const float* Wq = (const float*)d_in[1];
    const float* bq = (const float*)d_in[2];
    const float* Wk = (const float*)d_in[3];
    const float* bk = (const float*)d_in[4];
    const float* Wv = (const float*)d_in[5];
    const float* bv = (const float*)d_in[6];
    const float* Wo = (const float*)d_in[7];
    const float* bo = (const float*)d_in[8];
    float* out = (float*)d_out;

    __half *xh, *qp, *kp, *vp, *cp, *wtq, *wtk, *wtv, *wto;
    cudaGetSymbolAddress((void**)&xh, g_xh);
    cudaGetSymbolAddress((void**)&qp, g_q);
    cudaGetSymbolAddress((void**)&kp, g_k);
    cudaGetSymbolAddress((void**)&vp, g_v);
    cudaGetSymbolAddress((void**)&cp, g_ctx);
    cudaGetSymbolAddress((void**)&wtq, g_wtq);
    cudaGetSymbolAddress((void**)&wtk, g_wtk);
    cudaGetSymbolAddress((void**)&wtv, g_wtv);
    cudaGetSymbolAddress((void**)&wto, g_wto);

    cudaFuncSetAttribute(gemm_h_kernel,
                         cudaFuncAttributeMaxDynamicSharedMemorySize, G_SMEM);
    cudaFuncSetAttribute(attn_h_kernel,
                         cudaFuncAttributeMaxDynamicSharedMemorySize, A_SMEM);

    dim3 pgrid(32, 32, 5), pblock(32, 8);
    prep_kernel<<<pgrid, pblock>>>(x, xh, Wq, Wk, Wv, Wo, wtq, wtk, wtv, wto);

    const float qscale = 0.125f * 1.44269504f;  // fold 1/sqrt(64) * log2(e)

    dim3 ggrid3(HIDDEN / GN, MROWS / GM, 3);    // (8, 16, 3) = 384 CTAs
    gemm_h_kernel<<<ggrid3, 256, G_SMEM>>>(xh, wtq, wtk, wtv, bq, bk, bv,
                                           qp, kp, vp, 1, qscale);

    dim3 attn_grid(SEQ / 128, BATCH * HEADS);   // (16, 32)
    attn_h_kernel<<<attn_grid, 256, A_SMEM>>>(qp, kp, vp, cp);

    dim3 ggrid1(HIDDEN / GN, MROWS / GM, 1);    // (8, 16) = 128 CTAs
    gemm_h_kernel<<<ggrid1, 256, G_SMEM>>>(cp, wto, wto, wto, bo, bo, bo,
                                           out, out, out, 0, 1.0f);
}

// round 12
// speedup vs baseline: 1.0461x; 1.0461x over previous
#include <cuda_runtime.h>
#include <cuda_fp16.h>
#include <math.h>

#define HIDDEN   1024
#define HEADS    16
#define HEAD_DIM 64
#define BATCH    2
#define SEQ      2048
#define MROWS    (BATCH * SEQ)   // 4096

// Scratch (no cudaMalloc allowed)
__device__ __half g_xh[MROWS * HIDDEN];
__device__ __half g_q[MROWS * HIDDEN];
__device__ __half g_k[MROWS * HIDDEN];
__device__ __half g_v[MROWS * HIDDEN];
__device__ __half g_ctx[MROWS * HIDDEN];
__device__ __half g_wtq[HIDDEN * HIDDEN];
__device__ __half g_wtk[HIDDEN * HIDDEN];
__device__ __half g_wtv[HIDDEN * HIDDEN];
__device__ __half g_wto[HIDDEN * HIDDEN];

// ---------------------------------------------------------------------------
__device__ __forceinline__ unsigned smem_u32(const void* p) {
    unsigned a;
    asm("{ .reg .u64 t; cvta.to.shared.u64 t, %1; cvt.u32.u64 %0, t; }"
        : "=r"(a) : "l"(p));
    return a;
}

__device__ __forceinline__ unsigned pack_h2(float a, float b) {
    __half2 h = __floats2half2_rn(a, b);
    return *(unsigned*)&h;
}

__device__ __forceinline__ float ex2f(float x) {
    float r;
    asm("ex2.approx.f32 %0, %1;" : "=f"(r) : "f"(x));
    return r;
}

#define CP_ASYNC16(dst, src) \
    asm volatile("cp.async.cg.shared.global [%0], [%1], 16;" \
                 :: "r"(dst), "l"(src) : "memory")
#define CP_COMMIT() asm volatile("cp.async.commit_group;" ::: "memory")
#define CP_WAIT1()  asm volatile("cp.async.wait_group 1;" ::: "memory")
#define CP_WAIT0()  asm volatile("cp.async.wait_group 0;" ::: "memory")

#define LDMX4(r0, r1, r2, r3, addr) \
    asm volatile("ldmatrix.sync.aligned.m8n8.x4.shared.b16 {%0,%1,%2,%3}, [%4];" \
                 : "=r"(r0), "=r"(r1), "=r"(r2), "=r"(r3) : "r"(addr))
#define LDMX4T(r0, r1, r2, r3, addr) \
    asm volatile("ldmatrix.sync.aligned.m8n8.x4.trans.shared.b16 {%0,%1,%2,%3}, [%4];" \
                 : "=r"(r0), "=r"(r1), "=r"(r2), "=r"(r3) : "r"(addr))

// non-volatile: pure register op, scheduler-movable
__device__ __forceinline__ void mma_f16(float* d,
                                        unsigned a0, unsigned a1, unsigned a2, unsigned a3,
                                        unsigned b0, unsigned b1) {
    asm("mma.sync.aligned.m16n8k16.row.col.f32.f16.f16.f32 "
        "{%0,%1,%2,%3}, {%4,%5,%6,%7}, {%8,%9}, {%0,%1,%2,%3};\n"
        : "+f"(d[0]), "+f"(d[1]), "+f"(d[2]), "+f"(d[3])
        : "r"(a0), "r"(a1), "r"(a2), "r"(a3), "r"(b0), "r"(b1));
}

// ---------------------------------------------------------------------------
// Prep (one launch): z=0..3 -> weight transpose+fp16; z=4 -> x fp32->fp16
// ---------------------------------------------------------------------------
__global__ void __launch_bounds__(256) prep_kernel(
    const float* __restrict__ x, __half* __restrict__ xh,
    const float* __restrict__ s0, const float* __restrict__ s1,
    const float* __restrict__ s2, const float* __restrict__ s3,
    __half* __restrict__ d0, __half* __restrict__ d1,
    __half* __restrict__ d2, __half* __restrict__ d3)
{
    if (blockIdx.z == 4) {
        const int bid = blockIdx.y * 32 + blockIdx.x;
        const int tid = threadIdx.y * 32 + threadIdx.x;
        const size_t i = ((size_t)bid * 256 + tid) * 16;
        #pragma unroll
        for (int p = 0; p < 2; p++) {
            float4 a = *(const float4*)(x + i + 8 * p);
            float4 b = *(const float4*)(x + i + 8 * p + 4);
            uint4 u;
            u.x = pack_h2(a.x, a.y);
            u.y = pack_h2(a.z, a.w);
            u.z = pack_h2(b.x, b.y);
            u.w = pack_h2(b.z, b.w);
            *(uint4*)(xh + i + 8 * p) = u;
        }
        return;
    }
    const float* S;
    __half* D;
    switch (blockIdx.z) {
        case 0: S = s0; D = d0; break;
        case 1: S = s1; D = d1; break;
        case 2: S = s2; D = d2; break;
        default: S = s3; D = d3; break;
    }
    __shared__ float t[32][33];
    const int bx = blockIdx.x * 32, by = blockIdx.y * 32;
    #pragma unroll
    for (int i = 0; i < 4; i++)
        t[threadIdx.y + 8 * i][threadIdx.x] =
            S[(size_t)(by + threadIdx.y + 8 * i) * HIDDEN + bx + threadIdx.x];
    __syncthreads();
    #pragma unroll
    for (int i = 0; i < 4; i++)
        D[(size_t)(bx + threadIdx.y + 8 * i) * HIDDEN + by + threadIdx.x] =
            __float2half(t[threadIdx.x][threadIdx.y + 8 * i]);
}

// ---------------------------------------------------------------------------
// fp16 GEMM, z-fused: C_z = (Ah @ Bt_z^T + bias_z) * scale_z
// CTA 128x128, BK=64, 3-stage cp.async ring, 8 warps (4x2 of 32x64).
// NEW: register-level fragment double-buffering — LDSM for kk+1 issued
// before the kk HMMA burst, so HMMA never waits on a just-issued LDSM.
// ---------------------------------------------------------------------------
#define GSTRIDE 144
#define GSTAGE  (128 * GSTRIDE)       // 18432 per operand per stage
#define G_SMEM  (6 * GSTAGE)          // 110592

__global__ void __launch_bounds__(256, 2) gemm_h_kernel(
    const __half* __restrict__ Ah,
    const __half* __restrict__ B0, const __half* __restrict__ B1,
    const __half* __restrict__ B2,
    const float* __restrict__ bias0, const float* __restrict__ bias1,
    const float* __restrict__ bias2,
    void* __restrict__ C0, void* __restrict__ C1, void* __restrict__ C2,
    int out_half, float scale0)
{
    const __half* Bt;
    const float* bias;
    void* Cout;
    float scale = 1.0f;
    switch (blockIdx.z) {
        case 0:  Bt = B0; bias = bias0; Cout = C0; scale = scale0; break;
        case 1:  Bt = B1; bias = bias1; Cout = C1; break;
        default: Bt = B2; bias = bias2; Cout = C2; break;
    }

    extern __shared__ __align__(16) char smem[];
    const unsigned sbase = smem_u32(smem);
    const int tid  = threadIdx.x;
    const int lane = tid & 31;
    const int wid  = tid >> 5;
    const int g = lane >> 2, c = lane & 3;
    const int wm = (wid >> 1) * 32;
    const int wn = (wid & 1) * 64;
    const int bm = blockIdx.y * 128;
    const int bn = blockIdx.x * 128;

    const int lrow  = tid >> 1;
    const int lhalf = tid & 1;

    const unsigned a_lm = (unsigned)(wm + (lane & 15)) * GSTRIDE + (lane >> 4) * 16;
    const unsigned b_lm = (unsigned)(wn + (lane & 7)) * GSTRIDE + ((lane >> 3) & 1) * 16
                        + (lane >> 4) * 8 * GSTRIDE;

    const __half* Asrc = Ah + (size_t)(bm + lrow) * HIDDEN + lhalf * 32;
    const __half* Bsrc = Bt + (size_t)(bn + lrow) * HIDDEN + lhalf * 32;
    const unsigned a_dst0 = sbase + lrow * GSTRIDE + lhalf * 64;
    const unsigned b_dst0 = a_dst0 + GSTAGE;

    // prologue: prefetch chunks 0,1 into stages 0,1
    #pragma unroll
    for (int p = 0; p < 2; p++) {
        const unsigned so = p * 2 * GSTAGE;
        const int k0 = p * 64;
        #pragma unroll
        for (int j = 0; j < 4; j++) {
            CP_ASYNC16(a_dst0 + so + 16 * j, (const char*)(Asrc + k0) + 16 * j);
            CP_ASYNC16(b_dst0 + so + 16 * j, (const char*)(Bsrc + k0) + 16 * j);
        }
        CP_COMMIT();
    }

    float acc[2][8][4] = {};

    for (int i = 0; i < 16; i++) {
        const int st = i % 3;
        if (i < 15) CP_WAIT1(); else CP_WAIT0();
        __syncthreads();
        if (i < 14) {
            const unsigned so = ((i + 2) % 3) * 2 * GSTAGE;
            const int k1 = (i + 2) * 64;
            #pragma unroll
            for (int j = 0; j < 4; j++) {
                CP_ASYNC16(a_dst0 + so + 16 * j, (const char*)(Asrc + k1) + 16 * j);
                CP_ASYNC16(b_dst0 + so + 16 * j, (const char*)(Bsrc + k1) + 16 * j);
            }
            CP_COMMIT();
        }

        const unsigned a_s = sbase + st * 2 * GSTAGE;
        const unsigned b_s = a_s + GSTAGE;

        // fragment double-buffer: preload kk=0
        unsigned af[2][2][4], bf[2][4][4];
        #pragma unroll
        for (int mi = 0; mi < 2; mi++)
            LDMX4(af[0][mi][0], af[0][mi][1], af[0][mi][2], af[0][mi][3],
                  a_s + a_lm + mi * 16 * GSTRIDE);
        #pragma unroll
        for (int jj = 0; jj < 4; jj++)
            LDMX4(bf[0][jj][0], bf[0][jj][1], bf[0][jj][2], bf[0][jj][3],
                  b_s + b_lm + jj * 16 * GSTRIDE);

        #pragma unroll
        for (int kk = 0; kk < 4; kk++) {
            const int cur = kk & 1, nxt = cur ^ 1;
            if (kk < 3) {
                // issue LDSM for kk+1 BEFORE the kk HMMA burst
                #pragma unroll
                for (int mi = 0; mi < 2; mi++)
                    LDMX4(af[nxt][mi][0], af[nxt][mi][1], af[nxt][mi][2], af[nxt][mi][3],
                          a_s + a_lm + mi * 16 * GSTRIDE + (kk + 1) * 32);
                #pragma unroll
                for (int jj = 0; jj < 4; jj++)
                    LDMX4(bf[nxt][jj][0], bf[nxt][jj][1], bf[nxt][jj][2], bf[nxt][jj][3],
                          b_s + b_lm + jj * 16 * GSTRIDE + (kk + 1) * 32);
            }
            #pragma unroll
            for (int mi = 0; mi < 2; mi++)
                #pragma unroll
                for (int j = 0; j < 8; j++) {
                    const unsigned* b2 = &bf[cur][j >> 1][(j & 1) * 2];
                    mma_f16(acc[mi][j], af[cur][mi][0], af[cur][mi][1],
                            af[cur][mi][2], af[cur][mi][3], b2[0], b2[1]);
                }
        }
    }

    #pragma unroll
    for (int j = 0; j < 8; j++) {
        int col = bn + wn + 8 * j + 2 * c;
        float2 b2 = *(const float2*)(bias + col);
        #pragma unroll
        for (int mi = 0; mi < 2; mi++) {
            int row = bm + wm + 16 * mi + g;
            float v00 = (acc[mi][j][0] + b2.x) * scale;
            float v01 = (acc[mi][j][1] + b2.y) * scale;
            float v10 = (acc[mi][j][2] + b2.x) * scale;
            float v11 = (acc[mi][j][3] + b2.y) * scale;
            if (out_half) {
                __half* C = (__half*)Cout;
                *(unsigned*)(C + (size_t)row * HIDDEN + col)       = pack_h2(v00, v01);
                *(unsigned*)(C + (size_t)(row + 8) * HIDDEN + col) = pack_h2(v10, v11);
            } else {
                float* C = (float*)Cout;
                *(float2*)(C + (size_t)row * HIDDEN + col)       = make_float2(v00, v01);
                *(float2*)(C + (size_t)(row + 8) * HIDDEN + col) = make_float2(v10, v11);
            }
        }
    }
}

// ---------------------------------------------------------------------------
// Flash attention: 8 warps x 16 q rows, fp16 mma, MUFU/HMMA-interleaved
// streaming softmax, 3-stage cp.async ring (round-10 best, unchanged).
// ---------------------------------------------------------------------------
#define ASTRIDE 144
#define ATILE   (64 * ASTRIDE)   // 9216
#define A_SMEM  (6 * ATILE)      // 55296

__global__ void __launch_bounds__(256, 2) attn_h_kernel(
    const __half* __restrict__ Q, const __half* __restrict__ K,
    const __half* __restrict__ V, __half* __restrict__ Octx)
{
    extern __shared__ __align__(16) char smem[];
    const unsigned sbase = smem_u32(smem);

    const int tid  = threadIdx.x;
    const int lane = tid & 31;
    const int w    = tid >> 5;
    const int g = lane >> 2, c = lane & 3;
    const int bh = blockIdx.y;
    const int b = bh >> 4;
    const int h = bh & 15;
    const int q0 = blockIdx.x * 128;

    const __half* Qb = Q + (size_t)b * SEQ * HIDDEN + h * HEAD_DIM;
    const __half* Kb = K + (size_t)b * SEQ * HIDDEN + h * HEAD_DIM;
    const __half* Vb = V + (size_t)b * SEQ * HIDDEN + h * HEAD_DIM;

    const unsigned lm16 = (unsigned)(lane & 15) * ASTRIDE + (lane >> 4) * 16;
    const unsigned lmB  = (unsigned)(lane & 7) * ASTRIDE + ((lane >> 3) & 1) * 16
                        + (lane >> 4) * 8 * ASTRIDE;

    // ---- stage Q through smem (two 64-row halves), fragments in regs ----
    unsigned qa[4][4];
    {
        const int lr = tid >> 2;
        const int ls = tid & 3;
        #pragma unroll
        for (int half = 0; half < 2; half++) {
            __syncthreads();
            #pragma unroll
            for (int s = 0; s < 2; s++) {
                uint4 u = *(const uint4*)(Qb + (size_t)(q0 + 64 * half + lr) * HIDDEN + ls * 16 + 8 * s);
                *(uint4*)(smem + lr * ASTRIDE + ls * 32 + 16 * s) = u;
            }
            __syncthreads();
            if ((w >> 2) == half) {
                unsigned base = sbase + (unsigned)(w & 3) * 16 * ASTRIDE + lm16;
                #pragma unroll
                for (int kk = 0; kk < 4; kk++)
                    LDMX4(qa[kk][0], qa[kk][1], qa[kk][2], qa[kk][3], base + kk * 32);
            }
        }
        __syncthreads();
    }

    // pipeline loaders: 4 threads per row, 64 rows
    const int lr = tid >> 2;
    const int ls = tid & 3;
    const unsigned k_dst0 = sbase + lr * ASTRIDE + ls * 32;
    const unsigned v_dst0 = k_dst0 + ATILE;
    const __half* Ksrc = Kb + (size_t)lr * HIDDEN + ls * 16;
    const __half* Vsrc = Vb + (size_t)lr * HIDDEN + ls * 16;

    #pragma unroll
    for (int p = 0; p < 2; p++) {
        const unsigned so = p * 2 * ATILE;
        const size_t koff = (size_t)p * 64 * HIDDEN;
        #pragma unroll
        for (int s = 0; s < 2; s++) {
            CP_ASYNC16(k_dst0 + so + 16 * s, (const char*)(Ksrc + koff) + 16 * s);
            CP_ASYNC16(v_dst0 + so + 16 * s, (const char*)(Vsrc + koff) + 16 * s);
        }
        CP_COMMIT();
    }

    const unsigned onesB = (g == 0) ? 0x3C003C00u : 0u;
    const int NT = SEQ / 64;   // 32

    float o[8][4] = {};
    float ol[4] = {};

    for (int t = 0; t < NT; t++) {
        const int st = t % 3;
        if (t < NT - 1) CP_WAIT1(); else CP_WAIT0();
        __syncthreads();

        const unsigned ks = sbase + st * 2 * ATILE;
        const unsigned vs = ks + ATILE;

        // S = Q @ K^T (scores pre-scaled by 0.125*log2e via Q GEMM)
        float s[8][4] = {};
        #pragma unroll
        for (int kk = 0; kk < 4; kk++) {
            #pragma unroll
            for (int jj = 0; jj < 4; jj++) {
                unsigned bf0, bf1, bf2, bf3;
                LDMX4(bf0, bf1, bf2, bf3, ks + lmB + (unsigned)jj * 16 * ASTRIDE + kk * 32);
                mma_f16(s[2 * jj + 0], qa[kk][0], qa[kk][1], qa[kk][2], qa[kk][3], bf0, bf1);
                mma_f16(s[2 * jj + 1], qa[kk][0], qa[kk][1], qa[kk][2], qa[kk][3], bf2, bf3);
            }
        }

        // prefetch tile t+2 between S and PV
        if (t < NT - 2) {
            const unsigned so = ((t + 2) % 3) * 2 * ATILE;
            const size_t koff = (size_t)(t + 2) * 64 * HIDDEN;
            #pragma unroll
            for (int s2 = 0; s2 < 2; s2++) {
                CP_ASYNC16(k_dst0 + so + 16 * s2, (const char*)(Ksrc + koff) + 16 * s2);
                CP_ASYNC16(v_dst0 + so + 16 * s2, (const char*)(Vsrc + koff) + 16 * s2);
            }
            CP_COMMIT();
        }

        // fused softmax + PV: MUFU/pack interleave with 9 HMMA per kk
        #pragma unroll
        for (int kk = 0; kk < 4; kk++) {
            unsigned vf[4][4];
            #pragma unroll
            for (int dj = 0; dj < 4; dj++)
                LDMX4T(vf[dj][0], vf[dj][1], vf[dj][2], vf[dj][3],
                       vs + (unsigned)kk * 16 * ASTRIDE + lm16 + dj * 32);
            unsigned pa0 = pack_h2(ex2f(s[2 * kk][0]),     ex2f(s[2 * kk][1]));
            unsigned pa1 = pack_h2(ex2f(s[2 * kk][2]),     ex2f(s[2 * kk][3]));
            unsigned pa2 = pack_h2(ex2f(s[2 * kk + 1][0]), ex2f(s[2 * kk + 1][1]));
            unsigned pa3 = pack_h2(ex2f(s[2 * kk + 1][2]), ex2f(s[2 * kk + 1][3]));
            #pragma unroll
            for (int dj = 0; dj < 4; dj++) {
                mma_f16(o[2 * dj + 0], pa0, pa1, pa2, pa3, vf[dj][0], vf[dj][1]);
                mma_f16(o[2 * dj + 1], pa0, pa1, pa2, pa3, vf[dj][2], vf[dj][3]);
            }
            mma_f16(ol, pa0, pa1, pa2, pa3, onesB, onesB);
        }
    }

    const int qbase = lane & ~3;
    float l0 = __shfl_sync(0xffffffffu, ol[0], qbase);
    float l1 = __shfl_sync(0xffffffffu, ol[2], qbase);
    float inv0 = 1.f / l0;
    float inv1 = 1.f / l1;

    __half* Ob = Octx + ((size_t)b * SEQ + q0 + w * 16) * HIDDEN + h * HEAD_DIM;
    #pragma unroll
    for (int n = 0; n < 8; n++) {
        int col = 8 * n + 2 * c;
        *(unsigned*)(Ob + (size_t)g * HIDDEN + col) =
            pack_h2(o[n][0] * inv0, o[n][1] * inv0);
        *(unsigned*)(Ob + (size_t)(g + 8) * HIDDEN + col) =
            pack_h2(o[n][2] * inv1, o[n][3] * inv1);
    }
}

// ---------------------------------------------------------------------------
extern "C" void kernel_launch(void* const* d_in, const int* in_sizes, int n_in,
                              void* d_out, int out_size)
{
    const float* x  = (const float*)d_in[0];
    const float* Wq = (const float*)d_in[1];
    const float* bq = (const float*)d_in[2];
    const float* Wk = (const float*)d_in[3];
    const float* bk = (const float*)d_in[4];
    const float* Wv = (const float*)d_in[5];
    const float* bv = (const float*)d_in[6];
    const float* Wo = (const float*)d_in[7];
    const float* bo = (const float*)d_in[8];
    float* out = (float*)d_out;

    __half *xh, *qp, *kp, *vp, *cp, *wtq, *wtk, *wtv, *wto;
    cudaGetSymbolAddress((void**)&xh, g_xh);
    cudaGetSymbolAddress((void**)&qp, g_q);
    cudaGetSymbolAddress((void**)&kp, g_k);
    cudaGetSymbolAddress((void**)&vp, g_v);
    cudaGetSymbolAddress((void**)&cp, g_ctx);
    cudaGetSymbolAddress((void**)&wtq, g_wtq);
    cudaGetSymbolAddress((void**)&wtk, g_wtk);
    cudaGetSymbolAddress((void**)&wtv, g_wtv);
    cudaGetSymbolAddress((void**)&wto, g_wto);

    cudaFuncSetAttribute(gemm_h_kernel,
                         cudaFuncAttributeMaxDynamicSharedMemorySize, G_SMEM);
    cudaFuncSetAttribute(attn_h_kernel,
                         cudaFuncAttributeMaxDynamicSharedMemorySize, A_SMEM);

    dim3 pgrid(32, 32, 5), pblock(32, 8);
    prep_kernel<<<pgrid, pblock>>>(x, xh, Wq, Wk, Wv, Wo, wtq, wtk, wtv, wto);

    const float qscale = 0.125f * 1.44269504f;  // fold 1/sqrt(64) * log2(e)

    dim3 ggrid3(HIDDEN / 128, MROWS / 128, 3);  // fused Q/K/V: 768 CTAs
    gemm_h_kernel<<<ggrid3, 256, G_SMEM>>>(xh, wtq, wtk, wtv, bq, bk, bv,
                                           qp, kp, vp, 1, qscale);

    dim3 attn_grid(SEQ / 128, BATCH * HEADS);   // (16, 32)
    attn_h_kernel<<<attn_grid, 256, A_SMEM>>>(qp, kp, vp, cp);

    dim3 ggrid1(HIDDEN / 128, MROWS / 128, 1);  // 256 CTAs
    gemm_h_kernel<<<ggrid1, 256, G_SMEM>>>(cp, wto, wto, wto, bo, bo, bo,
                                           out, out, out, 0, 1.0f);
}

// round 14
// speedup vs baseline: 1.0514x; 1.0050x over previous
#include <cuda_runtime.h>
#include <cuda_fp16.h>
#include <math.h>

#define HIDDEN   1024
#define HEADS    16
#define HEAD_DIM 64
#define BATCH    2
#define SEQ      2048
#define MROWS    (BATCH * SEQ)   // 4096

// Scratch (no cudaMalloc allowed)
__device__ __half g_xh[MROWS * HIDDEN];
__device__ __half g_q[MROWS * HIDDEN];
__device__ __half g_k[MROWS * HIDDEN];
__device__ __half g_v[MROWS * HIDDEN];
__device__ __half g_ctx[MROWS * HIDDEN];
__device__ __half g_wtq[HIDDEN * HIDDEN];
__device__ __half g_wtk[HIDDEN * HIDDEN];
__device__ __half g_wtv[HIDDEN * HIDDEN];
__device__ __half g_wto[HIDDEN * HIDDEN];

// ---------------------------------------------------------------------------
__device__ __forceinline__ unsigned smem_u32(const void* p) {
    unsigned a;
    asm("{ .reg .u64 t; cvta.to.shared.u64 t, %1; cvt.u32.u64 %0, t; }"
        : "=r"(a) : "l"(p));
    return a;
}

__device__ __forceinline__ unsigned pack_h2(float a, float b) {
    __half2 h = __floats2half2_rn(a, b);
    return *(unsigned*)&h;
}

__device__ __forceinline__ float ex2f(float x) {
    float r;
    asm("ex2.approx.f32 %0, %1;" : "=f"(r) : "f"(x));
    return r;
}

#define CP_ASYNC16(dst, src) \
    asm volatile("cp.async.cg.shared.global [%0], [%1], 16;" \
                 :: "r"(dst), "l"(src) : "memory")
#define CP_COMMIT() asm volatile("cp.async.commit_group;" ::: "memory")
#define CP_WAIT1()  asm volatile("cp.async.wait_group 1;" ::: "memory")
#define CP_WAIT0()  asm volatile("cp.async.wait_group 0;" ::: "memory")

#define LDMX4(r0, r1, r2, r3, addr) \
    asm volatile("ldmatrix.sync.aligned.m8n8.x4.shared.b16 {%0,%1,%2,%3}, [%4];" \
                 : "=r"(r0), "=r"(r1), "=r"(r2), "=r"(r3) : "r"(addr))
#define LDMX4T(r0, r1, r2, r3, addr) \
    asm volatile("ldmatrix.sync.aligned.m8n8.x4.trans.shared.b16 {%0,%1,%2,%3}, [%4];" \
                 : "=r"(r0), "=r"(r1), "=r"(r2), "=r"(r3) : "r"(addr))

// non-volatile: pure register op, scheduler-movable
__device__ __forceinline__ void mma_f16(float* d,
                                        unsigned a0, unsigned a1, unsigned a2, unsigned a3,
                                        unsigned b0, unsigned b1) {
    asm("mma.sync.aligned.m16n8k16.row.col.f32.f16.f16.f32 "
        "{%0,%1,%2,%3}, {%4,%5,%6,%7}, {%8,%9}, {%0,%1,%2,%3};\n"
        : "+f"(d[0]), "+f"(d[1]), "+f"(d[2]), "+f"(d[3])
        : "r"(a0), "r"(a1), "r"(a2), "r"(a3), "r"(b0), "r"(b1));
}

// ---------------------------------------------------------------------------
// Prep (one launch): z=0..3 -> weight transpose+fp16; z=4 -> x fp32->fp16
// ---------------------------------------------------------------------------
__global__ void __launch_bounds__(256) prep_kernel(
    const float* __restrict__ x, __half* __restrict__ xh,
    const float* __restrict__ s0, const float* __restrict__ s1,
    const float* __restrict__ s2, const float* __restrict__ s3,
    __half* __restrict__ d0, __half* __restrict__ d1,
    __half* __restrict__ d2, __half* __restrict__ d3)
{
    if (blockIdx.z == 4) {
        const int bid = blockIdx.y * 32 + blockIdx.x;
        const int tid = threadIdx.y * 32 + threadIdx.x;
        const size_t i = ((size_t)bid * 256 + tid) * 16;
        #pragma unroll
        for (int p = 0; p < 2; p++) {
            float4 a = *(const float4*)(x + i + 8 * p);
            float4 b = *(const float4*)(x + i + 8 * p + 4);
            uint4 u;
            u.x = pack_h2(a.x, a.y);
            u.y = pack_h2(a.z, a.w);
            u.z = pack_h2(b.x, b.y);
            u.w = pack_h2(b.z, b.w);
            *(uint4*)(xh + i + 8 * p) = u;
        }
        return;
    }
    const float* S;
    __half* D;
    switch (blockIdx.z) {
        case 0: S = s0; D = d0; break;
        case 1: S = s1; D = d1; break;
        case 2: S = s2; D = d2; break;
        default: S = s3; D = d3; break;
    }
    __shared__ float t[32][33];
    const int bx = blockIdx.x * 32, by = blockIdx.y * 32;
    #pragma unroll
    for (int i = 0; i < 4; i++)
        t[threadIdx.y + 8 * i][threadIdx.x] =
            S[(size_t)(by + threadIdx.y + 8 * i) * HIDDEN + bx + threadIdx.x];
    __syncthreads();
    #pragma unroll
    for (int i = 0; i < 4; i++)
        D[(size_t)(bx + threadIdx.y + 8 * i) * HIDDEN + by + threadIdx.x] =
            __float2half(t[threadIdx.x][threadIdx.y + 8 * i]);
}

// ---------------------------------------------------------------------------
// fp16 GEMM, persistent over nz weight matrices:
//   for z in 0..nz-1:  C_z = (Ah @ Bt_z^T + bias_z) * scale_z
// CTA 128x128, BK=64, 8 warps (4x2), fragment double-buffering.
// Single cp.async 3-stage ring, CONTINUOUS across z boundaries (stage =
// global_chunk % 3) — the ring never drains; next-z loads overlap the
// previous z's epilogue. One wave of 256 CTAs.
// ---------------------------------------------------------------------------
#define GSTRIDE 144
#define GSTAGE  (128 * GSTRIDE)       // 18432 per operand per stage
#define G_SMEM  (6 * GSTAGE)          // 110592

#define BPTR(z)  ((z) == 0 ? B0 : ((z) == 1 ? B1 : B2))
#define BIASP(z) ((z) == 0 ? bias0 : ((z) == 1 ? bias1 : bias2))
#define CPTR(z)  ((z) == 0 ? C0 : ((z) == 1 ? C1 : C2))

__global__ void __launch_bounds__(256, 2) gemm_h_kernel(
    const __half* __restrict__ Ah,
    const __half* __restrict__ B0, const __half* __restrict__ B1,
    const __half* __restrict__ B2,
    const float* __restrict__ bias0, const float* __restrict__ bias1,
    const float* __restrict__ bias2,
    void* __restrict__ C0, void* __restrict__ C1, void* __restrict__ C2,
    int nz, int out_half, float scale0)
{
    extern __shared__ __align__(16) char smem[];
    const unsigned sbase = smem_u32(smem);
    const int tid  = threadIdx.x;
    const int lane = tid & 31;
    const int wid  = tid >> 5;
    const int g = lane >> 2, c = lane & 3;
    const int wm = (wid >> 1) * 32;
    const int wn = (wid & 1) * 64;
    const int bm = blockIdx.y * 128;
    const int bn = blockIdx.x * 128;

    const int lrow  = tid >> 1;
    const int lhalf = tid & 1;

    const unsigned a_lm = (unsigned)(wm + (lane & 15)) * GSTRIDE + (lane >> 4) * 16;
    const unsigned b_lm = (unsigned)(wn + (lane & 7)) * GSTRIDE + ((lane >> 3) & 1) * 16
                        + (lane >> 4) * 8 * GSTRIDE;

    const __half* Asrc = Ah + (size_t)(bm + lrow) * HIDDEN + lhalf * 32;
    const size_t  boff = (size_t)(bn + lrow) * HIDDEN + lhalf * 32;
    const unsigned a_dst0 = sbase + lrow * GSTRIDE + lhalf * 64;
    const unsigned b_dst0 = a_dst0 + GSTAGE;

    const int NG = nz * 16;   // global chunk count

    // prologue: prefetch global chunks 0,1 (z=0) into stages 0,1
    #pragma unroll
    for (int p = 0; p < 2; p++) {
        const unsigned so = p * 2 * GSTAGE;
        const int k0 = p * 64;
        #pragma unroll
        for (int j = 0; j < 4; j++) {
            CP_ASYNC16(a_dst0 + so + 16 * j, (const char*)(Asrc + k0) + 16 * j);
            CP_ASYNC16(b_dst0 + so + 16 * j, (const char*)(B0 + boff + k0) + 16 * j);
        }
        CP_COMMIT();
    }

    float acc[2][8][4] = {};

    for (int ig = 0; ig < NG; ig++) {
        const int st = ig % 3;
        if (ig < NG - 1) CP_WAIT1(); else CP_WAIT0();
        __syncthreads();

        const unsigned a_s = sbase + st * 2 * GSTAGE;
        const unsigned b_s = a_s + GSTAGE;

        // fragment double-buffer: preload kk=0 FIRST (fragment latency starts
        // draining before the cp.async burst hits the MIO queue)
        unsigned af[2][2][4], bf[2][4][4];
        #pragma unroll
        for (int mi = 0; mi < 2; mi++)
            LDMX4(af[0][mi][0], af[0][mi][1], af[0][mi][2], af[0][mi][3],
                  a_s + a_lm + mi * 16 * GSTRIDE);
        #pragma unroll
        for (int jj = 0; jj < 4; jj++)
            LDMX4(bf[0][jj][0], bf[0][jj][1], bf[0][jj][2], bf[0][jj][3],
                  b_s + b_lm + jj * 16 * GSTRIDE);

        // prefetch global chunk ig+2 (may belong to the NEXT z — ring never drains)
        if (ig + 2 < NG) {
            const int ig2 = ig + 2;
            const int z2 = ig2 >> 4;
            const int k1 = (ig2 & 15) * 64;
            const __half* B2src = BPTR(z2) + boff + k1;
            const unsigned so = (ig2 % 3) * 2 * GSTAGE;
            #pragma unroll
            for (int j = 0; j < 4; j++) {
                CP_ASYNC16(a_dst0 + so + 16 * j, (const char*)(Asrc + k1) + 16 * j);
                CP_ASYNC16(b_dst0 + so + 16 * j, (const char*)B2src + 16 * j);
            }
            CP_COMMIT();
        }

        #pragma unroll
        for (int kk = 0; kk < 4; kk++) {
            const int cur = kk & 1, nxt = cur ^ 1;
            if (kk < 3) {
                #pragma unroll
                for (int mi = 0; mi < 2; mi++)
                    LDMX4(af[nxt][mi][0], af[nxt][mi][1], af[nxt][mi][2], af[nxt][mi][3],
                          a_s + a_lm + mi * 16 * GSTRIDE + (kk + 1) * 32);
                #pragma unroll
                for (int jj = 0; jj < 4; jj++)
                    LDMX4(bf[nxt][jj][0], bf[nxt][jj][1], bf[nxt][jj][2], bf[nxt][jj][3],
                          b_s + b_lm + jj * 16 * GSTRIDE + (kk + 1) * 32);
            }
            #pragma unroll
            for (int mi = 0; mi < 2; mi++)
                #pragma unroll
                for (int j = 0; j < 8; j++) {
                    const unsigned* b2 = &bf[cur][j >> 1][(j & 1) * 2];
                    mma_f16(acc[mi][j], af[cur][mi][0], af[cur][mi][1],
                            af[cur][mi][2], af[cur][mi][3], b2[0], b2[1]);
                }
        }

        // end of a z-panel: epilogue (overlaps with already-inflight next-z loads)
        if ((ig & 15) == 15) {
            const int zc = ig >> 4;
            const float* bias = BIASP(zc);
            void* Cout = CPTR(zc);
            const float scale = (zc == 0) ? scale0 : 1.0f;
            #pragma unroll
            for (int j = 0; j < 8; j++) {
                int col = bn + wn + 8 * j + 2 * c;
                float2 b2 = *(const float2*)(bias + col);
                #pragma unroll
                for (int mi = 0; mi < 2; mi++) {
                    int row = bm + wm + 16 * mi + g;
                    float v00 = (acc[mi][j][0] + b2.x) * scale;
                    float v01 = (acc[mi][j][1] + b2.y) * scale;
                    float v10 = (acc[mi][j][2] + b2.x) * scale;
                    float v11 = (acc[mi][j][3] + b2.y) * scale;
                    if (out_half) {
                        __half* C = (__half*)Cout;
                        *(unsigned*)(C + (size_t)row * HIDDEN + col)       = pack_h2(v00, v01);
                        *(unsigned*)(C + (size_t)(row + 8) * HIDDEN + col) = pack_h2(v10, v11);
                    } else {
                        float* C = (float*)Cout;
                        *(float2*)(C + (size_t)row * HIDDEN + col)       = make_float2(v00, v01);
                        *(float2*)(C + (size_t)(row + 8) * HIDDEN + col) = make_float2(v10, v11);
                    }
                    acc[mi][j][0] = 0.f; acc[mi][j][1] = 0.f;
                    acc[mi][j][2] = 0.f; acc[mi][j][3] = 0.f;
                }
            }
        }
    }
}

// ---------------------------------------------------------------------------
// Flash attention: 8 warps x 16 q rows, fp16 mma, MUFU/HMMA-interleaved
// streaming softmax, 3-stage cp.async ring (round-10/12 best, unchanged).
// ---------------------------------------------------------------------------
#define ASTRIDE 144
#define ATILE   (64 * ASTRIDE)   // 9216
#define A_SMEM  (6 * ATILE)      // 55296

__global__ void __launch_bounds__(256, 2) attn_h_kernel(
    const __half* __restrict__ Q, const __half* __restrict__ K,
    const __half* __restrict__ V, __half* __restrict__ Octx)
{
    extern __shared__ __align__(16) char smem[];
    const unsigned sbase = smem_u32(smem);

    const int tid  = threadIdx.x;
    const int lane = tid & 31;
    const int w    = tid >> 5;
    const int g = lane >> 2, c = lane & 3;
    const int bh = blockIdx.y;
    const int b = bh >> 4;
    const int h = bh & 15;
    const int q0 = blockIdx.x * 128;

    const __half* Qb = Q + (size_t)b * SEQ * HIDDEN + h * HEAD_DIM;
    const __half* Kb = K + (size_t)b * SEQ * HIDDEN + h * HEAD_DIM;
    const __half* Vb = V + (size_t)b * SEQ * HIDDEN + h * HEAD_DIM;

    const unsigned lm16 = (unsigned)(lane & 15) * ASTRIDE + (lane >> 4) * 16;
    const unsigned lmB  = (unsigned)(lane & 7) * ASTRIDE + ((lane >> 3) & 1) * 16
                        + (lane >> 4) * 8 * ASTRIDE;

    // ---- stage Q through smem (two 64-row halves), fragments in regs ----
    unsigned qa[4][4];
    {
        const int lr = tid >> 2;
        const int ls = tid & 3;
        #pragma unroll
        for (int half = 0; half < 2; half++) {
            __syncthreads();
            #pragma unroll
            for (int s = 0; s < 2; s++) {
                uint4 u = *(const uint4*)(Qb + (size_t)(q0 + 64 * half + lr) * HIDDEN + ls * 16 + 8 * s);
                *(uint4*)(smem + lr * ASTRIDE + ls * 32 + 16 * s) = u;
            }
            __syncthreads();
            if ((w >> 2) == half) {
                unsigned base = sbase + (unsigned)(w & 3) * 16 * ASTRIDE + lm16;
                #pragma unroll
                for (int kk = 0; kk < 4; kk++)
                    LDMX4(qa[kk][0], qa[kk][1], qa[kk][2], qa[kk][3], base + kk * 32);
            }
        }
        __syncthreads();
    }

    // pipeline loaders: 4 threads per row, 64 rows
    const int lr = tid >> 2;
    const int ls = tid & 3;
    const unsigned k_dst0 = sbase + lr * ASTRIDE + ls * 32;
    const unsigned v_dst0 = k_dst0 + ATILE;
    const __half* Ksrc = Kb + (size_t)lr * HIDDEN + ls * 16;
    const __half* Vsrc = Vb + (size_t)lr * HIDDEN + ls * 16;

    #pragma unroll
    for (int p = 0; p < 2; p++) {
        const unsigned so = p * 2 * ATILE;
        const size_t koff = (size_t)p * 64 * HIDDEN;
        #pragma unroll
        for (int s = 0; s < 2; s++) {
            CP_ASYNC16(k_dst0 + so + 16 * s, (const char*)(Ksrc + koff) + 16 * s);
            CP_ASYNC16(v_dst0 + so + 16 * s, (const char*)(Vsrc + koff) + 16 * s);
        }
        CP_COMMIT();
    }

    const unsigned onesB = (g == 0) ? 0x3C003C00u : 0u;
    const int NT = SEQ / 64;   // 32

    float o[8][4] = {};
    float ol[4] = {};

    for (int t = 0; t < NT; t++) {
        const int st = t % 3;
        if (t < NT - 1) CP_WAIT1(); else CP_WAIT0();
        __syncthreads();

        const unsigned ks = sbase + st * 2 * ATILE;
        const unsigned vs = ks + ATILE;

        // S = Q @ K^T (scores pre-scaled by 0.125*log2e via Q GEMM)
        float s[8][4] = {};
        #pragma unroll
        for (int kk = 0; kk < 4; kk++) {
            #pragma unroll
            for (int jj = 0; jj < 4; jj++) {
                unsigned bf0, bf1, bf2, bf3;
                LDMX4(bf0, bf1, bf2, bf3, ks + lmB + (unsigned)jj * 16 * ASTRIDE + kk * 32);
                mma_f16(s[2 * jj + 0], qa[kk][0], qa[kk][1], qa[kk][2], qa[kk][3], bf0, bf1);
                mma_f16(s[2 * jj + 1], qa[kk][0], qa[kk][1], qa[kk][2], qa[kk][3], bf2, bf3);
            }
        }

        // prefetch tile t+2 between S and PV
        if (t < NT - 2) {
            const unsigned so = ((t + 2) % 3) * 2 * ATILE;
            const size_t koff = (size_t)(t + 2) * 64 * HIDDEN;
            #pragma unroll
            for (int s2 = 0; s2 < 2; s2++) {
                CP_ASYNC16(k_dst0 + so + 16 * s2, (const char*)(Ksrc + koff) + 16 * s2);
                CP_ASYNC16(v_dst0 + so + 16 * s2, (const char*)(Vsrc + koff) + 16 * s2);
            }
            CP_COMMIT();
        }

        // fused softmax + PV: MUFU/pack interleave with 9 HMMA per kk
        #pragma unroll
        for (int kk = 0; kk < 4; kk++) {
            unsigned vf[4][4];
            #pragma unroll
            for (int dj = 0; dj < 4; dj++)
                LDMX4T(vf[dj][0], vf[dj][1], vf[dj][2], vf[dj][3],
                       vs + (unsigned)kk * 16 * ASTRIDE + lm16 + dj * 32);
            unsigned pa0 = pack_h2(ex2f(s[2 * kk][0]),     ex2f(s[2 * kk][1]));
            unsigned pa1 = pack_h2(ex2f(s[2 * kk][2]),     ex2f(s[2 * kk][3]));
            unsigned pa2 = pack_h2(ex2f(s[2 * kk + 1][0]), ex2f(s[2 * kk + 1][1]));
            unsigned pa3 = pack_h2(ex2f(s[2 * kk + 1][2]), ex2f(s[2 * kk + 1][3]));
            #pragma unroll
            for (int dj = 0; dj < 4; dj++) {
                mma_f16(o[2 * dj + 0], pa0, pa1, pa2, pa3, vf[dj][0], vf[dj][1]);
                mma_f16(o[2 * dj + 1], pa0, pa1, pa2, pa3, vf[dj][2], vf[dj][3]);
            }
            mma_f16(ol, pa0, pa1, pa2, pa3, onesB, onesB);
        }
    }

    const int qbase = lane & ~3;
    float l0 = __shfl_sync(0xffffffffu, ol[0], qbase);
    float l1 = __shfl_sync(0xffffffffu, ol[2], qbase);
    float inv0 = 1.f / l0;
    float inv1 = 1.f / l1;

    __half* Ob = Octx + ((size_t)b * SEQ + q0 + w * 16) * HIDDEN + h * HEAD_DIM;
    #pragma unroll
    for (int n = 0; n < 8; n++) {
        int col = 8 * n + 2 * c;
        *(unsigned*)(Ob + (size_t)g * HIDDEN + col) =
            pack_h2(o[n][0] * inv0, o[n][1] * inv0);
        *(unsigned*)(Ob + (size_t)(g + 8) * HIDDEN + col) =
            pack_h2(o[n][2] * inv1, o[n][3] * inv1);
    }
}

// ---------------------------------------------------------------------------
extern "C" void kernel_launch(void* const* d_in, const int* in_sizes, int n_in,
                              void* d_out, int out_size)
{
    const float* x  = (const float*)d_in[0];
    const float* Wq = (const float*)d_in[1];
    const float* bq = (const float*)d_in[2];
    const float* Wk = (const float*)d_in[3];
    const float* bk = (const float*)d_in[4];
    const float* Wv = (const float*)d_in[5];
    const float* bv = (const float*)d_in[6];
    const float* Wo = (const float*)d_in[7];
    const float* bo = (const float*)d_in[8];
    float* out = (float*)d_out;

    __half *xh, *qp, *kp, *vp, *cp, *wtq, *wtk, *wtv, *wto;
    cudaGetSymbolAddress((void**)&xh, g_xh);
    cudaGetSymbolAddress((void**)&qp, g_q);
    cudaGetSymbolAddress((void**)&kp, g_k);
    cudaGetSymbolAddress((void**)&vp, g_v);
    cudaGetSymbolAddress((void**)&cp, g_ctx);
    cudaGetSymbolAddress((void**)&wtq, g_wtq);
    cudaGetSymbolAddress((void**)&wtk, g_wtk);
    cudaGetSymbolAddress((void**)&wtv, g_wtv);
    cudaGetSymbolAddress((void**)&wto, g_wto);

    cudaFuncSetAttribute(gemm_h_kernel,
                         cudaFuncAttributeMaxDynamicSharedMemorySize, G_SMEM);
    cudaFuncSetAttribute(attn_h_kernel,
                         cudaFuncAttributeMaxDynamicSharedMemorySize, A_SMEM);

    dim3 pgrid(32, 32, 5), pblock(32, 8);
    prep_kernel<<<pgrid, pblock>>>(x, xh, Wq, Wk, Wv, Wo, wtq, wtk, wtv, wto);

    const float qscale = 0.125f * 1.44269504f;  // fold 1/sqrt(64) * log2(e)

    // QKV: persistent — 256 CTAs (one wave), each does q,k,v panels
    dim3 ggrid(HIDDEN / 128, MROWS / 128);      // (8, 32) = 256 CTAs
    gemm_h_kernel<<<ggrid, 256, G_SMEM>>>(xh, wtq, wtk, wtv, bq, bk, bv,
                                          qp, kp, vp, 3, 1, qscale);

    dim3 attn_grid(SEQ / 128, BATCH * HEADS);   // (16, 32)
    attn_h_kernel<<<attn_grid, 256, A_SMEM>>>(qp, kp, vp, cp);

    gemm_h_kernel<<<ggrid, 256, G_SMEM>>>(cp, wto, wto, wto, bo, bo, bo,
                                          out, out, out, 1, 0, 1.0f);
}